// round 4
// baseline (speedup 1.0000x reference)
#include <cuda_runtime.h>

#define HEPS 1e-8f
#define HMAX_NORM 20.0f

__global__ void __launch_bounds__(256, 4)
hyperbolic_expmap_kernel(const float4* __restrict__ x,
                         const float4* __restrict__ v,
                         float4* __restrict__ out,
                         int nrows)
{
    int tid = blockIdx.x * blockDim.x + threadIdx.x;
    int row = tid >> 1;        // 2 threads per row, each owns 4 x float4
    int sub = tid & 1;
    if (row >= nrows) return;
    const bool lead = (sub == 0);   // owns the time coordinate (element 0)

    // Interleaved chunk ownership: chunks {sub, sub+2, sub+4, sub+6}.
    // Each LDG.128 pairs sub0/sub1 into a contiguous 32B sector per row.
    long base = (long)row * 8 + sub;

    // Issue all 8 loads up front (MLP=8), streaming (no reuse)
    float4 xa = __ldcs(&x[base + 0]);
    float4 xb = __ldcs(&x[base + 2]);
    float4 xc = __ldcs(&x[base + 4]);
    float4 xd = __ldcs(&x[base + 6]);
    float4 va = __ldcs(&v[base + 0]);
    float4 vb = __ldcs(&v[base + 2]);
    float4 vc = __ldcs(&v[base + 4]);
    float4 vd = __ldcs(&v[base + 6]);

    float xr[16] = {xa.x, xa.y, xa.z, xa.w, xb.x, xb.y, xb.z, xb.w,
                    xc.x, xc.y, xc.z, xc.w, xd.x, xd.y, xd.z, xd.w};
    float vr[16] = {va.x, va.y, va.z, va.w, vb.x, vb.y, vb.z, vb.w,
                    vc.x, vc.y, vc.z, vc.w, vd.x, vd.y, vd.z, vd.w};

    // ---- single fused reduction pass over ORIGINAL data ----
    float s = 0.f, xv = 0.f, vvm = 0.f;
#pragma unroll
    for (int i = 0; i < 16; i++) {
        float xi = xr[i], vi = vr[i];
        float sq = xi * xi;
        float p  = xi * vi;
        float q  = vi * vi;
        if (lead && i == 0) { sq = 0.f; p = 0.f; q = -q; }
        s += sq; xv += p; vvm += q;
    }
    s   += __shfl_xor_sync(0xffffffffu, s,   1);
    xv  += __shfl_xor_sync(0xffffffffu, xv,  1);
    vvm += __shfl_xor_sync(0xffffffffu, vvm, 1);
    float v0 = __shfl_sync(0xffffffffu, vr[0], 0, 2);  // time comp of v

    // ---- projection of x + Minkowski inner, analytically ----
    bool tiny = (s < HEPS);
    float t     = sqrtf(1.f + (tiny ? HEPS : s));   // new time coord of x
    float scale = tiny ? 0.f : 1.f;
    float inner = fmaf(-t, v0, scale * xv);         // <x_proj, v>_M

    // v_proj = v + inner * x_proj ; <v_p,v_p>_M = <v,v>_M + inner^2
#pragma unroll
    for (int i = 0; i < 16; i++) {
        float xp = scale * xr[i];
        if (lead && i == 0) xp = t;
        xr[i] = xp;
        vr[i] = fmaf(inner, xp, vr[i]);
    }
    float vv = fmaf(inner, inner, vvm);

    // ---- minkowski norm + cosh/sinh coefficients ----
    float a  = fabsf(vv);
    float vn = (a < HEPS) ? (sqrtf(a) * 0.5f) : sqrtf(a);
    vn = fminf(vn, HMAX_NORM);
    float c1, c2;
    if (vn < HEPS) { c1 = 1.f; c2 = 0.f; }
    else {
        float e  = __expf(vn);
        float ei = __expf(-vn);
        c1 = 0.5f * (e + ei);
        c2 = (0.5f * (e - ei)) / fmaxf(vn, HEPS);
    }

    // ---- result = c1*x_proj + c2*v_proj (reuse xr) ----
#pragma unroll
    for (int i = 0; i < 16; i++) xr[i] = fmaf(c2, vr[i], c1 * xr[i]);

    // ---- final projection, analytic:  s2 = c2^2*vv + r0^2 - c1^2 ----
    float vp0 = fmaf(inner, t, v0);           // lead's v_proj[0]
    float r0  = fmaf(c2, vp0, c1 * t);
    float s2  = fmaf(c2 * c2, vv, fmaf(r0, r0, -c1 * c1));

    bool tiny2 = (s2 < HEPS);
    float t2  = sqrtf(1.f + (tiny2 ? HEPS : s2));
    float sc2 = tiny2 ? 0.f : 1.f;
#pragma unroll
    for (int i = 0; i < 16; i++) xr[i] *= sc2;
    if (lead) xr[0] = t2;

    __stcs(&out[base + 0], make_float4(xr[0],  xr[1],  xr[2],  xr[3]));
    __stcs(&out[base + 2], make_float4(xr[4],  xr[5],  xr[6],  xr[7]));
    __stcs(&out[base + 4], make_float4(xr[8],  xr[9],  xr[10], xr[11]));
    __stcs(&out[base + 6], make_float4(xr[12], xr[13], xr[14], xr[15]));
}

extern "C" void kernel_launch(void* const* d_in, const int* in_sizes, int n_in,
                              void* d_out, int out_size) {
    const float4* x = (const float4*)d_in[0];
    const float4* v = (const float4*)d_in[1];
    float4* out = (float4*)d_out;
    int nrows = in_sizes[0] / 32;
    const int threads = 256;
    long total = (long)nrows * 2;
    int blocks = (int)((total + threads - 1) / threads);
    hyperbolic_expmap_kernel<<<blocks, threads>>>(x, v, out, nrows);
}

// round 6
// speedup vs baseline: 1.0241x; 1.0241x over previous
#include <cuda_runtime.h>

#define HEPS 1e-8f
#define HMAX_NORM 20.0f

__global__ void __launch_bounds__(256)
hyperbolic_expmap_kernel(const float4* __restrict__ x,
                         const float4* __restrict__ v,
                         float4* __restrict__ out,
                         int nrows)
{
    int tid  = blockIdx.x * blockDim.x + threadIdx.x;
    int slot = tid >> 3;          // 8 lanes per row -> full-line LDG.128
    int sub  = tid & 7;
    int half = (nrows + 1) >> 1;
    if (slot >= half) return;
    const bool lead = (sub == 0); // owns time coordinate (element 0)

    int rowA = slot;
    int rowB = slot + half;
    bool hasB = rowB < nrows;
    int rowBc = hasB ? rowB : rowA;

    long iA = (long)rowA  * 8 + sub;
    long iB = (long)rowBc * 8 + sub;

    // Front-batch 4 independent full-line loads (MLP=4, 1 wavefront/line)
    float4 xA4 = x[iA];
    float4 vA4 = v[iA];
    float4 xB4 = x[iB];
    float4 vB4 = v[iB];

    float xr[2][4] = {{xA4.x, xA4.y, xA4.z, xA4.w},
                      {xB4.x, xB4.y, xB4.z, xB4.w}};
    float vr[2][4] = {{vA4.x, vA4.y, vA4.z, vA4.w},
                      {vB4.x, vB4.y, vB4.z, vB4.w}};

    // ---- fused single-pass partials for both rows ----
    float s[2] = {0.f, 0.f}, xv[2] = {0.f, 0.f}, vvm[2] = {0.f, 0.f};
#pragma unroll
    for (int k = 0; k < 2; k++) {
#pragma unroll
        for (int i = 0; i < 4; i++) {
            float xi = xr[k][i], vi = vr[k][i];
            float sq = xi * xi;
            float p  = xi * vi;
            float q  = vi * vi;
            if (lead && i == 0) { sq = 0.f; p = 0.f; q = -q; }
            s[k] += sq; xv[k] += p; vvm[k] += q;
        }
    }
    // 6 independent butterfly chains, interleaved for ILP
#pragma unroll
    for (int m = 1; m <= 4; m <<= 1) {
#pragma unroll
        for (int k = 0; k < 2; k++) {
            s[k]   += __shfl_xor_sync(0xffffffffu, s[k],   m);
            xv[k]  += __shfl_xor_sync(0xffffffffu, xv[k],  m);
            vvm[k] += __shfl_xor_sync(0xffffffffu, vvm[k], m);
        }
    }
    float v0[2];
#pragma unroll
    for (int k = 0; k < 2; k++)
        v0[k] = __shfl_sync(0xffffffffu, vr[k][0], 0, 8);  // time comp of v

#pragma unroll
    for (int k = 0; k < 2; k++) {
        // ---- projection of x + Minkowski inner, analytically ----
        bool tiny = (s[k] < HEPS);
        float t     = sqrtf(1.f + (tiny ? HEPS : s[k]));
        float scale = tiny ? 0.f : 1.f;
        float inner = fmaf(-t, v0[k], scale * xv[k]);   // <x_proj, v>_M

        // v_proj = v + inner * x_proj ; <v_p,v_p>_M = <v,v>_M + inner^2
#pragma unroll
        for (int i = 0; i < 4; i++) {
            float xp = scale * xr[k][i];
            if (lead && i == 0) xp = t;
            xr[k][i] = xp;
            vr[k][i] = fmaf(inner, xp, vr[k][i]);
        }
        float vv = fmaf(inner, inner, vvm[k]);

        // ---- minkowski norm + cosh/sinh coefficients ----
        float a  = fabsf(vv);
        float vn = (a < HEPS) ? (sqrtf(a) * 0.5f) : sqrtf(a);
        vn = fminf(vn, HMAX_NORM);
        float c1, c2;
        if (vn < HEPS) { c1 = 1.f; c2 = 0.f; }
        else {
            float e  = __expf(vn);
            float ei = __expf(-vn);
            c1 = 0.5f * (e + ei);
            c2 = (0.5f * (e - ei)) / fmaxf(vn, HEPS);
        }

        // ---- result = c1*x_proj + c2*v_proj (reuse xr) ----
#pragma unroll
        for (int i = 0; i < 4; i++)
            xr[k][i] = fmaf(c2, vr[k][i], c1 * xr[k][i]);

        // ---- final projection, analytic: s2 = c2^2*vv + r0^2 - c1^2 ----
        float vp0 = fmaf(inner, t, v0[k]);     // lead's v_proj[0]
        float r0  = fmaf(c2, vp0, c1 * t);
        float s2  = fmaf(c2 * c2, vv, fmaf(r0, r0, -c1 * c1));

        bool tiny2 = (s2 < HEPS);
        float t2  = sqrtf(1.f + (tiny2 ? HEPS : s2));
        float sc2 = tiny2 ? 0.f : 1.f;
#pragma unroll
        for (int i = 0; i < 4; i++) xr[k][i] *= sc2;
        if (lead) xr[k][0] = t2;
    }

    out[iA] = make_float4(xr[0][0], xr[0][1], xr[0][2], xr[0][3]);
    if (hasB)
        out[iB] = make_float4(xr[1][0], xr[1][1], xr[1][2], xr[1][3]);
}

extern "C" void kernel_launch(void* const* d_in, const int* in_sizes, int n_in,
                              void* d_out, int out_size) {
    const float4* x = (const float4*)d_in[0];
    const float4* v = (const float4*)d_in[1];
    float4* out = (float4*)d_out;
    int nrows = in_sizes[0] / 32;
    int half  = (nrows + 1) >> 1;
    const int threads = 256;
    long total = (long)half * 8;
    int blocks = (int)((total + threads - 1) / threads);
    hyperbolic_expmap_kernel<<<blocks, threads>>>(x, v, out, nrows);
}

// round 7
// speedup vs baseline: 1.0655x; 1.0405x over previous
#include <cuda_runtime.h>

#define HEPS 1e-8f
#define HMAX_NORM 20.0f

__global__ void __launch_bounds__(256)
hyperbolic_expmap_kernel(const float4* __restrict__ x,
                         const float4* __restrict__ v,
                         float4* __restrict__ out,
                         int nrows)
{
    int tid = blockIdx.x * blockDim.x + threadIdx.x;
    int row = tid >> 2;        // 4 threads per row, each owns 2 x float4
    int sub = tid & 3;
    if (row >= nrows) return;
    const bool lead = (sub == 0);   // owns the time coordinate (element 0)

    long idx0 = (long)row * 8 + sub;   // bytes [64*sub, 64*sub+16)  of the row
    long idx1 = idx0 + 4;              // second half-line chunk

    // Front-batch 4 independent loads (MLP=4, contiguous 64B per 4 lanes)
    float4 xa = x[idx0];
    float4 xb = x[idx1];
    float4 va = v[idx0];
    float4 vb = v[idx1];

    float xr[8] = {xa.x, xa.y, xa.z, xa.w, xb.x, xb.y, xb.z, xb.w};
    float vr[8] = {va.x, va.y, va.z, va.w, vb.x, vb.y, vb.z, vb.w};

    // ---- single fused reduction pass over ORIGINAL data ----
    // s   = sum_space x_i^2 ; xv = sum_space x_i v_i ; vvm = <v,v>_Minkowski
    float s = 0.f, xv = 0.f, vvm = 0.f;
#pragma unroll
    for (int i = 0; i < 8; i++) {
        float xi = xr[i], vi = vr[i];
        float sq = xi * xi;
        float p  = xi * vi;
        float q  = vi * vi;
        if (lead && i == 0) { sq = 0.f; p = 0.f; q = -q; }
        s += sq; xv += p; vvm += q;
    }
#pragma unroll
    for (int m = 1; m <= 2; m <<= 1) {
        s   += __shfl_xor_sync(0xffffffffu, s,   m);
        xv  += __shfl_xor_sync(0xffffffffu, xv,  m);
        vvm += __shfl_xor_sync(0xffffffffu, vvm, m);
    }
    float v0 = __shfl_sync(0xffffffffu, vr[0], 0, 4);  // time comp of v

    // ---- all scalar math (group-uniform) ----
    bool  tiny  = (s < HEPS);
    float t     = sqrtf(1.f + (tiny ? HEPS : s));   // projected time coord
    float scale = tiny ? 0.f : 1.f;
    float inner = fmaf(-t, v0, scale * xv);         // <x_proj, v>_M
    float vv    = fmaf(inner, inner, vvm);          // <v_proj, v_proj>_M

    float a  = fabsf(vv);
    float vn = (a < HEPS) ? (sqrtf(a) * 0.5f) : sqrtf(a);
    vn = fminf(vn, HMAX_NORM);
    float c1, c2;
    if (vn < HEPS) { c1 = 1.f; c2 = 0.f; }
    else {
        float e  = __expf(vn);
        float ei = __expf(-vn);
        c1 = 0.5f * (e + ei);
        c2 = (0.5f * (e - ei)) / fmaxf(vn, HEPS);
    }

    // result = c1*x_p + c2*(v + inner*x_p) = A*x_p + c2*v,  A = c1 + c2*inner
    float A  = fmaf(c2, inner, c1);
    float r0 = fmaf(A, t, c2 * v0);                 // result time coord
    // final projection: s2 = c2^2*vv + r0^2 - c1^2
    float s2 = fmaf(c2 * c2, vv, fmaf(r0, r0, -c1 * c1));
    bool  tiny2 = (s2 < HEPS);
    float t2  = sqrtf(1.f + (tiny2 ? HEPS : s2));
    float sc2 = tiny2 ? 0.f : 1.f;

    // fold everything into one linear combination of the ORIGINAL loads
    float C1 = sc2 * (A * scale);   // coefficient on x (space components)
    float C2 = sc2 * c2;            // coefficient on v

    float r[8];
#pragma unroll
    for (int i = 0; i < 8; i++) r[i] = fmaf(C1, xr[i], C2 * vr[i]);
    if (lead) r[0] = t2;

    __stcs(&out[idx0], make_float4(r[0], r[1], r[2], r[3]));
    __stcs(&out[idx1], make_float4(r[4], r[5], r[6], r[7]));
}

extern "C" void kernel_launch(void* const* d_in, const int* in_sizes, int n_in,
                              void* d_out, int out_size) {
    const float4* x = (const float4*)d_in[0];
    const float4* v = (const float4*)d_in[1];
    float4* out = (float4*)d_out;
    int nrows = in_sizes[0] / 32;
    const int threads = 256;
    long total = (long)nrows * 4;
    int blocks = (int)((total + threads - 1) / threads);
    hyperbolic_expmap_kernel<<<blocks, threads>>>(x, v, out, nrows);
}